// round 1
// baseline (speedup 1.0000x reference)
#include <cuda_runtime.h>

#define NB 16384
#define NI 512
#define NO 2048

// scratch (device globals — no allocations allowed)
__device__ float g_xinv[NB];
__device__ float g_winv[NO];
__device__ float g_cos[(size_t)NB * NO];

// ---------------------------------------------------------------------------
// Row inverse L2 norms: one 128-thread block per row, one float4 per thread.
// inv = 1 / max(||row||, 1e-8)
// ---------------------------------------------------------------------------
__global__ void xnorm_kernel(const float* __restrict__ X) {
    const int row = blockIdx.x;
    float4 v = reinterpret_cast<const float4*>(X + (size_t)row * NI)[threadIdx.x];
    float s = v.x * v.x + v.y * v.y + v.z * v.z + v.w * v.w;
#pragma unroll
    for (int o = 16; o; o >>= 1) s += __shfl_xor_sync(0xffffffffu, s, o);
    __shared__ float ws[4];
    if ((threadIdx.x & 31) == 0) ws[threadIdx.x >> 5] = s;
    __syncthreads();
    if (threadIdx.x == 0) {
        float t = ws[0] + ws[1] + ws[2] + ws[3];
        g_xinv[row] = 1.0f / fmaxf(sqrtf(t), 1e-8f);
    }
}

__global__ void wnorm_kernel(const float* __restrict__ W) {
    const int row = blockIdx.x;
    float4 v = reinterpret_cast<const float4*>(W + (size_t)row * NI)[threadIdx.x];
    float s = v.x * v.x + v.y * v.y + v.z * v.z + v.w * v.w;
#pragma unroll
    for (int o = 16; o; o >>= 1) s += __shfl_xor_sync(0xffffffffu, s, o);
    __shared__ float ws[4];
    if ((threadIdx.x & 31) == 0) ws[threadIdx.x >> 5] = s;
    __syncthreads();
    if (threadIdx.x == 0) {
        float t = ws[0] + ws[1] + ws[2] + ws[3];
        g_winv[row] = 1.0f / fmaxf(sqrtf(t), 1e-8f);
    }
}

// ---------------------------------------------------------------------------
// SGEMM: cos[b,o] = xinv[b]*winv[o] * dot(X[b,:], W[o,:])
// 128x128 tile, BK=16, double-buffered smem, 256 threads,
// warps 4x2, lanes 4x8, 8x8 microtile per thread.
// ---------------------------------------------------------------------------
__global__ __launch_bounds__(256, 2) void gemm_kernel(
    const float* __restrict__ X, const float* __restrict__ W) {
    __shared__ float As[2][16][128];
    __shared__ float Bs[2][16][128];

    const int tid = threadIdx.x;
    const int m0 = blockIdx.y * 128;
    const int n0 = blockIdx.x * 128;

    const int warp = tid >> 5;
    const int lane = tid & 31;
    const int rowFrag = (warp >> 1) * 32 + (lane >> 3) * 8;  // 0..120
    const int colFrag = (warp & 1) * 64 + (lane & 7) * 8;    // 0..120

    // global-load mapping: 4 threads cover one row's 16-float k-slice
    const int lrow = tid >> 2;        // 0..63 (plus +64 for second half)
    const int lk4 = (tid & 3) * 4;    // 0,4,8,12

    const float* xg = X + (size_t)m0 * NI;
    const float* wg = W + (size_t)n0 * NI;

    float acc[8][8];
#pragma unroll
    for (int i = 0; i < 8; i++)
#pragma unroll
        for (int j = 0; j < 8; j++) acc[i][j] = 0.0f;

    // prologue: tile 0 -> buffer 0
    {
#pragma unroll
        for (int j = 0; j < 2; j++) {
            const int row = lrow + j * 64;
            float4 va = *reinterpret_cast<const float4*>(xg + (size_t)row * NI + lk4);
            float4 vb = *reinterpret_cast<const float4*>(wg + (size_t)row * NI + lk4);
            As[0][lk4 + 0][row] = va.x; As[0][lk4 + 1][row] = va.y;
            As[0][lk4 + 2][row] = va.z; As[0][lk4 + 3][row] = va.w;
            Bs[0][lk4 + 0][row] = vb.x; Bs[0][lk4 + 1][row] = vb.y;
            Bs[0][lk4 + 2][row] = vb.z; Bs[0][lk4 + 3][row] = vb.w;
        }
    }
    __syncthreads();

    int buf = 0;
    const int KT = NI / 16;  // 32
    for (int kt = 0; kt < KT; kt++) {
        float4 pa[2], pb[2];
        if (kt < KT - 1) {
            const int kbase = (kt + 1) * 16;
#pragma unroll
            for (int j = 0; j < 2; j++) {
                const int row = lrow + j * 64;
                pa[j] = *reinterpret_cast<const float4*>(xg + (size_t)row * NI + kbase + lk4);
                pb[j] = *reinterpret_cast<const float4*>(wg + (size_t)row * NI + kbase + lk4);
            }
        }
#pragma unroll
        for (int k = 0; k < 16; k++) {
            float a[8], b[8];
            *reinterpret_cast<float4*>(&a[0]) = *reinterpret_cast<const float4*>(&As[buf][k][rowFrag]);
            *reinterpret_cast<float4*>(&a[4]) = *reinterpret_cast<const float4*>(&As[buf][k][rowFrag + 4]);
            *reinterpret_cast<float4*>(&b[0]) = *reinterpret_cast<const float4*>(&Bs[buf][k][colFrag]);
            *reinterpret_cast<float4*>(&b[4]) = *reinterpret_cast<const float4*>(&Bs[buf][k][colFrag + 4]);
#pragma unroll
            for (int i = 0; i < 8; i++)
#pragma unroll
                for (int j = 0; j < 8; j++)
                    acc[i][j] = fmaf(a[i], b[j], acc[i][j]);
        }
        if (kt < KT - 1) {
            buf ^= 1;
#pragma unroll
            for (int j = 0; j < 2; j++) {
                const int row = lrow + j * 64;
                As[buf][lk4 + 0][row] = pa[j].x; As[buf][lk4 + 1][row] = pa[j].y;
                As[buf][lk4 + 2][row] = pa[j].z; As[buf][lk4 + 3][row] = pa[j].w;
                Bs[buf][lk4 + 0][row] = pb[j].x; Bs[buf][lk4 + 1][row] = pb[j].y;
                Bs[buf][lk4 + 2][row] = pb[j].z; Bs[buf][lk4 + 3][row] = pb[j].w;
            }
            __syncthreads();
        }
    }

    // epilogue: scale by xinv*winv, store cosine
    float wi[8];
    *reinterpret_cast<float4*>(&wi[0]) = *reinterpret_cast<const float4*>(&g_winv[n0 + colFrag]);
    *reinterpret_cast<float4*>(&wi[4]) = *reinterpret_cast<const float4*>(&g_winv[n0 + colFrag + 4]);
#pragma unroll
    for (int i = 0; i < 8; i++) {
        const float xi = g_xinv[m0 + rowFrag + i];
        float* dst = g_cos + (size_t)(m0 + rowFrag + i) * NO + n0 + colFrag;
        float4 o0, o1;
        o0.x = acc[i][0] * xi * wi[0]; o0.y = acc[i][1] * xi * wi[1];
        o0.z = acc[i][2] * xi * wi[2]; o0.w = acc[i][3] * xi * wi[3];
        o1.x = acc[i][4] * xi * wi[4]; o1.y = acc[i][5] * xi * wi[5];
        o1.z = acc[i][6] * xi * wi[6]; o1.w = acc[i][7] * xi * wi[7];
        *reinterpret_cast<float4*>(dst) = o0;
        *reinterpret_cast<float4*>(dst + 4) = o1;
    }
}

// ---------------------------------------------------------------------------
// Per-row epilogue: mean/max/argmax over 2048 cosines, nonlinearity,
// adaptive threshold, WTA. One 256-thread block per row; 8 elems/thread.
// ---------------------------------------------------------------------------
__global__ __launch_bounds__(256) void spike_kernel(
    const float* __restrict__ th, float* __restrict__ out) {
    const int row = blockIdx.x;
    const int tid = threadIdx.x;
    const float* crow = g_cos + (size_t)row * NO;
    const int base = tid * 8;

    float v[8];
    *reinterpret_cast<float4*>(&v[0]) = *reinterpret_cast<const float4*>(crow + base);
    *reinterpret_cast<float4*>(&v[4]) = *reinterpret_cast<const float4*>(crow + base + 4);

    float s = 0.0f, mx = -3.402823466e+38f;
    int mi = 0;
#pragma unroll
    for (int e = 0; e < 8; e++) {
        s += v[e];
        if (v[e] > mx) { mx = v[e]; mi = base + e; }
    }
    // warp reduce (sum; argmax with first-index tie-break)
#pragma unroll
    for (int o = 16; o; o >>= 1) {
        s += __shfl_xor_sync(0xffffffffu, s, o);
        float omx = __shfl_xor_sync(0xffffffffu, mx, o);
        int omi = __shfl_xor_sync(0xffffffffu, mi, o);
        if (omx > mx || (omx == mx && omi < mi)) { mx = omx; mi = omi; }
    }
    __shared__ float ssum[8], smax[8];
    __shared__ int sidx[8];
    __shared__ float sh_mu, sh_q;
    __shared__ int sh_arg;
    if ((tid & 31) == 0) { ssum[tid >> 5] = s; smax[tid >> 5] = mx; sidx[tid >> 5] = mi; }
    __syncthreads();
    if (tid == 0) {
        float ts = 0.0f, tm = -3.402823466e+38f;
        int ti = 0;
#pragma unroll
        for (int w = 0; w < 8; w++) {
            ts += ssum[w];
            if (smax[w] > tm || (smax[w] == tm && sidx[w] < ti)) { tm = smax[w]; ti = sidx[w]; }
        }
        const float mu = ts * (1.0f / NO);
        const float c = tm - mu;
        const float a = fabsf(c);
        const float vmax = copysignf((a + 10.0f * a * a * a) * 50.0f, c);
        sh_mu = mu;
        sh_q = vmax * 0.25f;
        sh_arg = ti;
    }
    __syncthreads();
    const float mu = sh_mu;
    const float q = sh_q;
    const int argi = sh_arg;

    float t[8];
    *reinterpret_cast<float4*>(&t[0]) = *reinterpret_cast<const float4*>(th + base);
    *reinterpret_cast<float4*>(&t[4]) = *reinterpret_cast<const float4*>(th + base + 4);

    float sp[8];
    int any = 0;
#pragma unroll
    for (int e = 0; e < 8; e++) {
        const float c = v[e] - mu;
        const float a = fabsf(c);
        const float vm = copysignf((a + 10.0f * a * a * a) * 50.0f, c);
        const float eff = fmaxf(fminf(t[e], q), 0.01f);
        sp[e] = (vm >= eff) ? 1.0f : 0.0f;
        any |= (vm >= eff);
    }
    const int anyb = __syncthreads_or(any);
    if (!anyb) {
#pragma unroll
        for (int e = 0; e < 8; e++) sp[e] = (base + e == argi) ? 1.0f : 0.0f;
    }
    float* dst = out + (size_t)row * NO + base;
    *reinterpret_cast<float4*>(dst) = *reinterpret_cast<float4*>(&sp[0]);
    *reinterpret_cast<float4*>(dst + 4) = *reinterpret_cast<float4*>(&sp[4]);
}

// ---------------------------------------------------------------------------
extern "C" void kernel_launch(void* const* d_in, const int* in_sizes, int n_in,
                              void* d_out, int out_size) {
    const float* X = (const float*)d_in[0];   // [16384, 512]
    const float* W = (const float*)d_in[1];   // [2048, 512]
    const float* TH = (const float*)d_in[2];  // [2048]
    float* OUT = (float*)d_out;               // [16384, 2048]

    xnorm_kernel<<<NB, 128>>>(X);
    wnorm_kernel<<<NO, 128>>>(W);
    gemm_kernel<<<dim3(NO / 128, NB / 128), 256>>>(X, W);
    spike_kernel<<<NB, 256>>>(TH, OUT);
}

// round 4
// speedup vs baseline: 1.1078x; 1.1078x over previous
#include <cuda_runtime.h>
#include <cstdint>

#define NB 16384
#define NI 512
#define NO 2048

#define BM 128
#define BN 64
#define BK 32
#define KCH (NI / BK)     // 16
#define STAGES 3
#define THREADS 256
#define ASTRIDE 36        // padded floats per row (conflict-free frag loads)
#define ATILE_F (128 * ASTRIDE)   // 4608
#define BTILE_F (64 * ASTRIDE)    // 2304
#define SMEM_BYTES (STAGES * (ATILE_F + BTILE_F) * 4)   // 82944

// ---------------------------------------------------------------------------
// scratch (device globals — no allocations allowed)
// ---------------------------------------------------------------------------
__device__ float g_xinv[NB];
__device__ float g_winv[NO];
__device__ float g_cos[(size_t)NB * NO];

// ---------------------------------------------------------------------------
// PTX helpers (sm_80-era features only: cp.async + warp mma.sync)
// ---------------------------------------------------------------------------
__device__ __forceinline__ uint32_t smem_u32(const void* p) {
    uint32_t a;
    asm("{ .reg .u64 t; cvta.to.shared.u64 t, %1; cvt.u32.u64 %0, t; }" : "=r"(a) : "l"(p));
    return a;
}
__device__ __forceinline__ void cp_async16(uint32_t dst, const void* src) {
    asm volatile("cp.async.cg.shared.global [%0], [%1], 16;" :: "r"(dst), "l"(src));
}
__device__ __forceinline__ void cp_commit() {
    asm volatile("cp.async.commit_group;" ::: "memory");
}
template <int N>
__device__ __forceinline__ void cp_wait() {
    asm volatile("cp.async.wait_group %0;" :: "n"(N) : "memory");
}
__device__ __forceinline__ void tf32_split(float x, uint32_t& hi, uint32_t& lo) {
    asm("cvt.rna.tf32.f32 %0, %1;" : "=r"(hi) : "f"(x));
    float r = x - __uint_as_float(hi);
    asm("cvt.rna.tf32.f32 %0, %1;" : "=r"(lo) : "f"(r));
}
// d += a*b  (accumulate in place)
__device__ __forceinline__ void mma_acc(float* d, const uint32_t* a, const uint32_t* b) {
    asm volatile(
        "mma.sync.aligned.m16n8k8.row.col.f32.tf32.tf32.f32 "
        "{%0,%1,%2,%3}, {%4,%5,%6,%7}, {%8,%9}, {%0,%1,%2,%3};"
        : "+f"(d[0]), "+f"(d[1]), "+f"(d[2]), "+f"(d[3])
        : "r"(a[0]), "r"(a[1]), "r"(a[2]), "r"(a[3]), "r"(b[0]), "r"(b[1]));
}
// d = a*b  (c = 0: starts a fresh short accumulation chain)
__device__ __forceinline__ void mma_zero(float* d, const uint32_t* a, const uint32_t* b) {
    asm volatile(
        "mma.sync.aligned.m16n8k8.row.col.f32.tf32.tf32.f32 "
        "{%0,%1,%2,%3}, {%4,%5,%6,%7}, {%8,%9}, {%10,%11,%12,%13};"
        : "=f"(d[0]), "=f"(d[1]), "=f"(d[2]), "=f"(d[3])
        : "r"(a[0]), "r"(a[1]), "r"(a[2]), "r"(a[3]), "r"(b[0]), "r"(b[1]),
          "f"(0.0f), "f"(0.0f), "f"(0.0f), "f"(0.0f));
}

// ---------------------------------------------------------------------------
// Row inverse L2 norms
// ---------------------------------------------------------------------------
__global__ void xnorm_kernel(const float* __restrict__ X) {
    const int row = blockIdx.x;
    float4 v = reinterpret_cast<const float4*>(X + (size_t)row * NI)[threadIdx.x];
    float s = v.x * v.x + v.y * v.y + v.z * v.z + v.w * v.w;
#pragma unroll
    for (int o = 16; o; o >>= 1) s += __shfl_xor_sync(0xffffffffu, s, o);
    __shared__ float ws[4];
    if ((threadIdx.x & 31) == 0) ws[threadIdx.x >> 5] = s;
    __syncthreads();
    if (threadIdx.x == 0) {
        float t = ws[0] + ws[1] + ws[2] + ws[3];
        g_xinv[row] = 1.0f / fmaxf(sqrtf(t), 1e-8f);
    }
}
__global__ void wnorm_kernel(const float* __restrict__ W) {
    const int row = blockIdx.x;
    float4 v = reinterpret_cast<const float4*>(W + (size_t)row * NI)[threadIdx.x];
    float s = v.x * v.x + v.y * v.y + v.z * v.z + v.w * v.w;
#pragma unroll
    for (int o = 16; o; o >>= 1) s += __shfl_xor_sync(0xffffffffu, s, o);
    __shared__ float ws[4];
    if ((threadIdx.x & 31) == 0) ws[threadIdx.x >> 5] = s;
    __syncthreads();
    if (threadIdx.x == 0) {
        float t = ws[0] + ws[1] + ws[2] + ws[3];
        g_winv[row] = 1.0f / fmaxf(sqrtf(t), 1e-8f);
    }
}

// ---------------------------------------------------------------------------
// 3xTF32 warp-mma GEMM with short tensor-accumulation chains:
//   cos[b,o] = xinv[b]*winv[o]*dot(X[b,:],W[o,:])
// CTA 128x64x32 tiles, 3-stage cp.async, 8 warps (2m x 4n), warp 64x16.
// Every 2 k-steps: temp frag (chain of 6 MMAs from zero) flushed into the
// fp32 master accumulator with RN adds on CUDA cores.
// ---------------------------------------------------------------------------
__global__ __launch_bounds__(THREADS, 2)
void gemm_tc(const float* __restrict__ X, const float* __restrict__ W) {
    extern __shared__ float smem[];
    float* Asm = smem;                      // [STAGES][128][ASTRIDE]
    float* Bsm = smem + STAGES * ATILE_F;   // [STAGES][64][ASTRIDE]

    const int tid = threadIdx.x;
    const int wid = tid >> 5;
    const int lane = tid & 31;
    const int m0 = blockIdx.y * BM;
    const int n0 = blockIdx.x * BN;
    const int warpM = wid & 1;   // 2
    const int warpN = wid >> 1;  // 4
    const int g = lane >> 2;     // 0..7
    const int t4 = lane & 3;     // 0..3

    const uint32_t sA = smem_u32(Asm);
    const uint32_t sB = smem_u32(Bsm);

    float master[4][2][4];
#pragma unroll
    for (int i = 0; i < 4; i++)
#pragma unroll
        for (int j = 0; j < 2; j++)
#pragma unroll
            for (int e = 0; e < 4; e++) master[i][j][e] = 0.0f;

    auto issue = [&](int kc, int st) {
        const int kbase = kc * BK;
        // A tile: 128x32 floats = 1024 float4 ; B tile: 64x32 = 512 float4
#pragma unroll
        for (int t = 0; t < 6; t++) {
            const int i = t * THREADS + tid;      // 0..1535
            if (i < 1024) {
                const int row = i >> 3;
                const int c4 = (i & 7) * 4;
                const uint32_t soff = (uint32_t)(st * ATILE_F + row * ASTRIDE + c4) * 4u;
                cp_async16(sA + soff, X + (size_t)(m0 + row) * NI + kbase + c4);
            } else {
                const int j = i - 1024;
                const int row = j >> 3;
                const int c4 = (j & 7) * 4;
                const uint32_t soff = (uint32_t)(st * BTILE_F + row * ASTRIDE + c4) * 4u;
                cp_async16(sB + soff, W + (size_t)(n0 + row) * NI + kbase + c4);
            }
        }
        cp_commit();
    };

    issue(0, 0);
    issue(1, 1);
    issue(2, 2);

    for (int kc = 0; kc < KCH; kc++) {
        cp_wait<STAGES - 1>();
        __syncthreads();
        const int st = kc % STAGES;
        const float* At = Asm + st * ATILE_F;
        const float* Bt = Bsm + st * BTILE_F;

#pragma unroll
        for (int half = 0; half < 2; half++) {
            float temp[4][2][4];
#pragma unroll
            for (int ks2 = 0; ks2 < 2; ks2++) {
                const int k0 = (half * 2 + ks2) * 8 + t4;
                // B fragments (shared across all mt)
                uint32_t bh[2][2], bl[2][2];
#pragma unroll
                for (int nt = 0; nt < 2; nt++) {
                    const int col = warpN * 16 + nt * 8 + g;
                    tf32_split(Bt[col * ASTRIDE + k0],     bh[nt][0], bl[nt][0]);
                    tf32_split(Bt[col * ASTRIDE + k0 + 4], bh[nt][1], bl[nt][1]);
                }
#pragma unroll
                for (int mt = 0; mt < 4; mt++) {
                    const int row = warpM * 64 + mt * 16 + g;
                    uint32_t ah[4], al[4];
                    tf32_split(At[row * ASTRIDE + k0],           ah[0], al[0]);
                    tf32_split(At[(row + 8) * ASTRIDE + k0],     ah[1], al[1]);
                    tf32_split(At[row * ASTRIDE + k0 + 4],       ah[2], al[2]);
                    tf32_split(At[(row + 8) * ASTRIDE + k0 + 4], ah[3], al[3]);
#pragma unroll
                    for (int nt = 0; nt < 2; nt++) {
                        if (ks2 == 0) mma_zero(temp[mt][nt], ah, bh[nt]);  // fresh chain
                        else          mma_acc(temp[mt][nt], ah, bh[nt]);
                        mma_acc(temp[mt][nt], ah, bl[nt]);   // hi*lo
                        mma_acc(temp[mt][nt], al, bh[nt]);   // lo*hi
                    }
                }
            }
            // flush short chain into RN fp32 master
#pragma unroll
            for (int mt = 0; mt < 4; mt++)
#pragma unroll
                for (int nt = 0; nt < 2; nt++)
#pragma unroll
                    for (int e = 0; e < 4; e++)
                        master[mt][nt][e] += temp[mt][nt][e];
        }
        __syncthreads();
        if (kc + STAGES < KCH) issue(kc + STAGES, st);
        else cp_commit();   // empty group keeps wait_group accounting uniform
    }

    // epilogue: scale by xinv*winv, store cosine (float2 per frag row)
#pragma unroll
    for (int mt = 0; mt < 4; mt++) {
        const int r0 = m0 + warpM * 64 + mt * 16 + g;
        const int r1 = r0 + 8;
        const float xi0 = g_xinv[r0];
        const float xi1 = g_xinv[r1];
#pragma unroll
        for (int nt = 0; nt < 2; nt++) {
            const int c = n0 + warpN * 16 + nt * 8 + t4 * 2;
            const float2 wv = *reinterpret_cast<const float2*>(g_winv + c);
            float2 o0, o1;
            o0.x = master[mt][nt][0] * xi0 * wv.x;
            o0.y = master[mt][nt][1] * xi0 * wv.y;
            o1.x = master[mt][nt][2] * xi1 * wv.x;
            o1.y = master[mt][nt][3] * xi1 * wv.y;
            *reinterpret_cast<float2*>(g_cos + (size_t)r0 * NO + c) = o0;
            *reinterpret_cast<float2*>(g_cos + (size_t)r1 * NO + c) = o1;
        }
    }
}

// ---------------------------------------------------------------------------
// Per-row epilogue: mean/max/argmax over 2048 cosines, nonlinearity,
// adaptive threshold, WTA. One 256-thread block per row; 8 elems/thread.
// ---------------------------------------------------------------------------
__global__ __launch_bounds__(256) void spike_kernel(
    const float* __restrict__ th, float* __restrict__ out) {
    const int row = blockIdx.x;
    const int tid = threadIdx.x;
    const float* crow = g_cos + (size_t)row * NO;
    const int base = tid * 8;

    float v[8];
    *reinterpret_cast<float4*>(&v[0]) = *reinterpret_cast<const float4*>(crow + base);
    *reinterpret_cast<float4*>(&v[4]) = *reinterpret_cast<const float4*>(crow + base + 4);

    float s = 0.0f, mx = -3.402823466e+38f;
    int mi = 0;
#pragma unroll
    for (int e = 0; e < 8; e++) {
        s += v[e];
        if (v[e] > mx) { mx = v[e]; mi = base + e; }
    }
#pragma unroll
    for (int o = 16; o; o >>= 1) {
        s += __shfl_xor_sync(0xffffffffu, s, o);
        float omx = __shfl_xor_sync(0xffffffffu, mx, o);
        int omi = __shfl_xor_sync(0xffffffffu, mi, o);
        if (omx > mx || (omx == mx && omi < mi)) { mx = omx; mi = omi; }
    }
    __shared__ float ssum[8], smax[8];
    __shared__ int sidx[8];
    __shared__ float sh_mu, sh_q;
    __shared__ int sh_arg;
    if ((tid & 31) == 0) { ssum[tid >> 5] = s; smax[tid >> 5] = mx; sidx[tid >> 5] = mi; }
    __syncthreads();
    if (tid == 0) {
        float ts = 0.0f, tm = -3.402823466e+38f;
        int ti = 0;
#pragma unroll
        for (int w = 0; w < 8; w++) {
            ts += ssum[w];
            if (smax[w] > tm || (smax[w] == tm && sidx[w] < ti)) { tm = smax[w]; ti = sidx[w]; }
        }
        const float mu = ts * (1.0f / NO);
        const float c = tm - mu;
        const float a = fabsf(c);
        const float vmax = copysignf((a + 10.0f * a * a * a) * 50.0f, c);
        sh_mu = mu;
        sh_q = vmax * 0.25f;
        sh_arg = ti;
    }
    __syncthreads();
    const float mu = sh_mu;
    const float q = sh_q;
    const int argi = sh_arg;

    float t[8];
    *reinterpret_cast<float4*>(&t[0]) = *reinterpret_cast<const float4*>(th + base);
    *reinterpret_cast<float4*>(&t[4]) = *reinterpret_cast<const float4*>(th + base + 4);

    float sp[8];
    int any = 0;
#pragma unroll
    for (int e = 0; e < 8; e++) {
        const float c = v[e] - mu;
        const float a = fabsf(c);
        const float vm = copysignf((a + 10.0f * a * a * a) * 50.0f, c);
        const float eff = fmaxf(fminf(t[e], q), 0.01f);
        sp[e] = (vm >= eff) ? 1.0f : 0.0f;
        any |= (vm >= eff);
    }
    const int anyb = __syncthreads_or(any);
    if (!anyb) {
#pragma unroll
        for (int e = 0; e < 8; e++) sp[e] = (base + e == argi) ? 1.0f : 0.0f;
    }
    float* dst = out + (size_t)row * NO + base;
    *reinterpret_cast<float4*>(dst) = *reinterpret_cast<float4*>(&sp[0]);
    *reinterpret_cast<float4*>(dst + 4) = *reinterpret_cast<float4*>(&sp[4]);
}

// ---------------------------------------------------------------------------
extern "C" void kernel_launch(void* const* d_in, const int* in_sizes, int n_in,
                              void* d_out, int out_size) {
    const float* X = (const float*)d_in[0];   // [16384, 512]
    const float* W = (const float*)d_in[1];   // [2048, 512]
    const float* TH = (const float*)d_in[2];  // [2048]
    float* OUT = (float*)d_out;               // [16384, 2048]

    cudaFuncSetAttribute(gemm_tc, cudaFuncAttributeMaxDynamicSharedMemorySize, SMEM_BYTES);

    xnorm_kernel<<<NB, 128>>>(X);
    wnorm_kernel<<<NO, 128>>>(W);
    gemm_tc<<<dim3(NO / BN, NB / BM), THREADS, SMEM_BYTES>>>(X, W);
    spike_kernel<<<NB, 256>>>(TH, OUT);
}

// round 5
// speedup vs baseline: 1.2088x; 1.0912x over previous
#include <cuda_runtime.h>
#include <cstdint>

#define NB 16384
#define NI 512
#define NO 2048

#define BM 128
#define BN 64
#define BK 32
#define KCH (NI / BK)     // 16
#define THREADS 256
#define ASTRIDE 36
#define APLANE (128 * ASTRIDE)            // 4608 floats
#define BPLANE (64 * ASTRIDE)             // 2304 floats
#define STAGE_F (2 * APLANE + 2 * BPLANE) // 13824 floats per stage
#define SMEM_BYTES (2 * STAGE_F * 4)      // 110592 B

// ---------------------------------------------------------------------------
// scratch (device globals — no allocations allowed)
// ---------------------------------------------------------------------------
__device__ float g_xinv[NB];
__device__ float g_winv[NO];
__device__ float g_cos[(size_t)NB * NO];

// ---------------------------------------------------------------------------
// helpers
// ---------------------------------------------------------------------------
__device__ __forceinline__ void tf32_split(float x, uint32_t& hi, uint32_t& lo) {
    asm("cvt.rna.tf32.f32 %0, %1;" : "=r"(hi) : "f"(x));
    float r = x - __uint_as_float(hi);
    asm("cvt.rna.tf32.f32 %0, %1;" : "=r"(lo) : "f"(r));
}
// d += a*b
__device__ __forceinline__ void mma_acc(float* d, const uint32_t* a, const uint32_t* b) {
    asm volatile(
        "mma.sync.aligned.m16n8k8.row.col.f32.tf32.tf32.f32 "
        "{%0,%1,%2,%3}, {%4,%5,%6,%7}, {%8,%9}, {%0,%1,%2,%3};"
        : "+f"(d[0]), "+f"(d[1]), "+f"(d[2]), "+f"(d[3])
        : "r"(a[0]), "r"(a[1]), "r"(a[2]), "r"(a[3]), "r"(b[0]), "r"(b[1]));
}
// d = a*b (fresh chain)
__device__ __forceinline__ void mma_zero(float* d, const uint32_t* a, const uint32_t* b) {
    asm volatile(
        "mma.sync.aligned.m16n8k8.row.col.f32.tf32.tf32.f32 "
        "{%0,%1,%2,%3}, {%4,%5,%6,%7}, {%8,%9}, {%10,%11,%12,%13};"
        : "=f"(d[0]), "=f"(d[1]), "=f"(d[2]), "=f"(d[3])
        : "r"(a[0]), "r"(a[1]), "r"(a[2]), "r"(a[3]), "r"(b[0]), "r"(b[1]),
          "f"(0.0f), "f"(0.0f), "f"(0.0f), "f"(0.0f));
}

// ---------------------------------------------------------------------------
// Row inverse L2 norms
// ---------------------------------------------------------------------------
__global__ void xnorm_kernel(const float* __restrict__ X) {
    const int row = blockIdx.x;
    float4 v = reinterpret_cast<const float4*>(X + (size_t)row * NI)[threadIdx.x];
    float s = v.x * v.x + v.y * v.y + v.z * v.z + v.w * v.w;
#pragma unroll
    for (int o = 16; o; o >>= 1) s += __shfl_xor_sync(0xffffffffu, s, o);
    __shared__ float ws[4];
    if ((threadIdx.x & 31) == 0) ws[threadIdx.x >> 5] = s;
    __syncthreads();
    if (threadIdx.x == 0) {
        float t = ws[0] + ws[1] + ws[2] + ws[3];
        g_xinv[row] = 1.0f / fmaxf(sqrtf(t), 1e-8f);
    }
}
__global__ void wnorm_kernel(const float* __restrict__ W) {
    const int row = blockIdx.x;
    float4 v = reinterpret_cast<const float4*>(W + (size_t)row * NI)[threadIdx.x];
    float s = v.x * v.x + v.y * v.y + v.z * v.z + v.w * v.w;
#pragma unroll
    for (int o = 16; o; o >>= 1) s += __shfl_xor_sync(0xffffffffu, s, o);
    __shared__ float ws[4];
    if ((threadIdx.x & 31) == 0) ws[threadIdx.x >> 5] = s;
    __syncthreads();
    if (threadIdx.x == 0) {
        float t = ws[0] + ws[1] + ws[2] + ws[3];
        g_winv[row] = 1.0f / fmaxf(sqrtf(t), 1e-8f);
    }
}

// ---------------------------------------------------------------------------
// 3xTF32 warp-mma GEMM, pre-split hi/lo smem planes:
//   cos[b,o] = xinv[b]*winv[o]*dot(X[b,:],W[o,:])
// CTA 128x64x32, 2-stage smem + register prefetch, 8 warps (2m x 4n),
// warp 64x16. Per kc: temp frag (12-MMA chain from zero) flushed into the
// fp32 master accumulator with RN adds on CUDA cores.
// ---------------------------------------------------------------------------
__global__ __launch_bounds__(THREADS, 2)
void gemm_tc(const float* __restrict__ X, const float* __restrict__ W) {
    extern __shared__ float smem[];   // [2 stages][Ahi|Alo|Bhi|Blo]

    const int tid = threadIdx.x;
    const int wid = tid >> 5;
    const int lane = tid & 31;
    const int m0 = blockIdx.y * BM;
    const int n0 = blockIdx.x * BN;
    const int warpM = wid & 1;   // 2
    const int warpN = wid >> 1;  // 4
    const int g = lane >> 2;     // 0..7
    const int t4 = lane & 3;     // 0..3

    // global-load mapping: 8 threads per row (float4 each)
    const int arow[4] = { (0 * THREADS + tid) >> 3, (1 * THREADS + tid) >> 3,
                          (2 * THREADS + tid) >> 3, (3 * THREADS + tid) >> 3 };
    const int brow[2] = { (0 * THREADS + tid) >> 3, (1 * THREADS + tid) >> 3 };
    const int c4 = (tid & 7) * 4;

    float master[4][2][4];
#pragma unroll
    for (int i = 0; i < 4; i++)
#pragma unroll
        for (int j = 0; j < 2; j++)
#pragma unroll
            for (int e = 0; e < 4; e++) master[i][j][e] = 0.0f;

    float4 ra[4], rb[2];   // single prefetch register set

    auto ldg = [&](int kc) {
        const int kbase = kc * BK + c4;
#pragma unroll
        for (int t = 0; t < 4; t++)
            ra[t] = *reinterpret_cast<const float4*>(X + (size_t)(m0 + arow[t]) * NI + kbase);
#pragma unroll
        for (int t = 0; t < 2; t++)
            rb[t] = *reinterpret_cast<const float4*>(W + (size_t)(n0 + brow[t]) * NI + kbase);
    };
    auto sts = [&](int st) {
        float* Ah = smem + st * STAGE_F;
        float* Al = Ah + APLANE;
        float* Bh = Al + APLANE;
        float* Bl = Bh + BPLANE;
#pragma unroll
        for (int t = 0; t < 4; t++) {
            uint32_t h0, l0, h1, l1, h2, l2, h3, l3;
            tf32_split(ra[t].x, h0, l0); tf32_split(ra[t].y, h1, l1);
            tf32_split(ra[t].z, h2, l2); tf32_split(ra[t].w, h3, l3);
            float* dh = Ah + arow[t] * ASTRIDE + c4;
            float* dl = Al + arow[t] * ASTRIDE + c4;
            *reinterpret_cast<uint4*>(dh) = make_uint4(h0, h1, h2, h3);
            *reinterpret_cast<uint4*>(dl) = make_uint4(l0, l1, l2, l3);
        }
#pragma unroll
        for (int t = 0; t < 2; t++) {
            uint32_t h0, l0, h1, l1, h2, l2, h3, l3;
            tf32_split(rb[t].x, h0, l0); tf32_split(rb[t].y, h1, l1);
            tf32_split(rb[t].z, h2, l2); tf32_split(rb[t].w, h3, l3);
            float* dh = Bh + brow[t] * ASTRIDE + c4;
            float* dl = Bl + brow[t] * ASTRIDE + c4;
            *reinterpret_cast<uint4*>(dh) = make_uint4(h0, h1, h2, h3);
            *reinterpret_cast<uint4*>(dl) = make_uint4(l0, l1, l2, l3);
        }
    };

    ldg(0);
    sts(0);
    ldg(1);

    for (int kc = 0; kc < KCH; kc++) {
        __syncthreads();
        const int cur = kc & 1;
        const uint32_t* Ah = reinterpret_cast<const uint32_t*>(smem + cur * STAGE_F);
        const uint32_t* Al = Ah + APLANE;
        const uint32_t* Bh = Al + APLANE;
        const uint32_t* Bl = Bh + BPLANE;

        float temp[4][2][4];
#pragma unroll
        for (int ks = 0; ks < 4; ks++) {
            const int k0 = ks * 8 + t4;
            uint32_t bh[2][2], bl[2][2];
#pragma unroll
            for (int nt = 0; nt < 2; nt++) {
                const int col = warpN * 16 + nt * 8 + g;
                bh[nt][0] = Bh[col * ASTRIDE + k0];
                bh[nt][1] = Bh[col * ASTRIDE + k0 + 4];
                bl[nt][0] = Bl[col * ASTRIDE + k0];
                bl[nt][1] = Bl[col * ASTRIDE + k0 + 4];
            }
#pragma unroll
            for (int mt = 0; mt < 4; mt++) {
                const int row = warpM * 64 + mt * 16 + g;
                uint32_t ah[4], al[4];
                ah[0] = Ah[row * ASTRIDE + k0];
                ah[1] = Ah[(row + 8) * ASTRIDE + k0];
                ah[2] = Ah[row * ASTRIDE + k0 + 4];
                ah[3] = Ah[(row + 8) * ASTRIDE + k0 + 4];
                al[0] = Al[row * ASTRIDE + k0];
                al[1] = Al[(row + 8) * ASTRIDE + k0];
                al[2] = Al[row * ASTRIDE + k0 + 4];
                al[3] = Al[(row + 8) * ASTRIDE + k0 + 4];
#pragma unroll
                for (int nt = 0; nt < 2; nt++) {
                    if (ks == 0) mma_zero(temp[mt][nt], ah, bh[nt]);
                    else         mma_acc(temp[mt][nt], ah, bh[nt]);
                    mma_acc(temp[mt][nt], ah, bl[nt]);   // hi*lo
                    mma_acc(temp[mt][nt], al, bh[nt]);   // lo*hi
                }
            }
        }
        // flush 12-MMA chain into RN fp32 master
#pragma unroll
        for (int mt = 0; mt < 4; mt++)
#pragma unroll
            for (int nt = 0; nt < 2; nt++)
#pragma unroll
                for (int e = 0; e < 4; e++)
                    master[mt][nt][e] += temp[mt][nt][e];

        if (kc + 1 < KCH) {
            sts((kc + 1) & 1);
            if (kc + 2 < KCH) ldg(kc + 2);
        }
    }

    // epilogue: scale by xinv*winv, store cosine (float2 per frag row)
#pragma unroll
    for (int mt = 0; mt < 4; mt++) {
        const int r0 = m0 + warpM * 64 + mt * 16 + g;
        const int r1 = r0 + 8;
        const float xi0 = g_xinv[r0];
        const float xi1 = g_xinv[r1];
#pragma unroll
        for (int nt = 0; nt < 2; nt++) {
            const int c = n0 + warpN * 16 + nt * 8 + t4 * 2;
            const float2 wv = *reinterpret_cast<const float2*>(g_winv + c);
            float2 o0, o1;
            o0.x = master[mt][nt][0] * xi0 * wv.x;
            o0.y = master[mt][nt][1] * xi0 * wv.y;
            o1.x = master[mt][nt][2] * xi1 * wv.x;
            o1.y = master[mt][nt][3] * xi1 * wv.y;
            *reinterpret_cast<float2*>(g_cos + (size_t)r0 * NO + c) = o0;
            *reinterpret_cast<float2*>(g_cos + (size_t)r1 * NO + c) = o1;
        }
    }
}

// ---------------------------------------------------------------------------
// Per-row epilogue: mean/max/argmax over 2048 cosines, nonlinearity,
// adaptive threshold, WTA. One 256-thread block per row; 8 elems/thread.
// ---------------------------------------------------------------------------
__global__ __launch_bounds__(256) void spike_kernel(
    const float* __restrict__ th, float* __restrict__ out) {
    const int row = blockIdx.x;
    const int tid = threadIdx.x;
    const float* crow = g_cos + (size_t)row * NO;
    const int base = tid * 8;

    float v[8];
    *reinterpret_cast<float4*>(&v[0]) = *reinterpret_cast<const float4*>(crow + base);
    *reinterpret_cast<float4*>(&v[4]) = *reinterpret_cast<const float4*>(crow + base + 4);

    float s = 0.0f, mx = -3.402823466e+38f;
    int mi = 0;
#pragma unroll
    for (int e = 0; e < 8; e++) {
        s += v[e];
        if (v[e] > mx) { mx = v[e]; mi = base + e; }
    }
#pragma unroll
    for (int o = 16; o; o >>= 1) {
        s += __shfl_xor_sync(0xffffffffu, s, o);
        float omx = __shfl_xor_sync(0xffffffffu, mx, o);
        int omi = __shfl_xor_sync(0xffffffffu, mi, o);
        if (omx > mx || (omx == mx && omi < mi)) { mx = omx; mi = omi; }
    }
    __shared__ float ssum[8], smax[8];
    __shared__ int sidx[8];
    __shared__ float sh_mu, sh_q;
    __shared__ int sh_arg;
    if ((tid & 31) == 0) { ssum[tid >> 5] = s; smax[tid >> 5] = mx; sidx[tid >> 5] = mi; }
    __syncthreads();
    if (tid == 0) {
        float ts = 0.0f, tm = -3.402823466e+38f;
        int ti = 0;
#pragma unroll
        for (int w = 0; w < 8; w++) {
            ts += ssum[w];
            if (smax[w] > tm || (smax[w] == tm && sidx[w] < ti)) { tm = smax[w]; ti = sidx[w]; }
        }
        const float mu = ts * (1.0f / NO);
        const float c = tm - mu;
        const float a = fabsf(c);
        const float vmax = copysignf((a + 10.0f * a * a * a) * 50.0f, c);
        sh_mu = mu;
        sh_q = vmax * 0.25f;
        sh_arg = ti;
    }
    __syncthreads();
    const float mu = sh_mu;
    const float q = sh_q;
    const int argi = sh_arg;

    float t[8];
    *reinterpret_cast<float4*>(&t[0]) = *reinterpret_cast<const float4*>(th + base);
    *reinterpret_cast<float4*>(&t[4]) = *reinterpret_cast<const float4*>(th + base + 4);

    float sp[8];
    int any = 0;
#pragma unroll
    for (int e = 0; e < 8; e++) {
        const float c = v[e] - mu;
        const float a = fabsf(c);
        const float vm = copysignf((a + 10.0f * a * a * a) * 50.0f, c);
        const float eff = fmaxf(fminf(t[e], q), 0.01f);
        sp[e] = (vm >= eff) ? 1.0f : 0.0f;
        any |= (vm >= eff);
    }
    const int anyb = __syncthreads_or(any);
    if (!anyb) {
#pragma unroll
        for (int e = 0; e < 8; e++) sp[e] = (base + e == argi) ? 1.0f : 0.0f;
    }
    float* dst = out + (size_t)row * NO + base;
    *reinterpret_cast<float4*>(dst) = *reinterpret_cast<float4*>(&sp[0]);
    *reinterpret_cast<float4*>(dst + 4) = *reinterpret_cast<float4*>(&sp[4]);
}

// ---------------------------------------------------------------------------
extern "C" void kernel_launch(void* const* d_in, const int* in_sizes, int n_in,
                              void* d_out, int out_size) {
    const float* X = (const float*)d_in[0];   // [16384, 512]
    const float* W = (const float*)d_in[1];   // [2048, 512]
    const float* TH = (const float*)d_in[2];  // [2048]
    float* OUT = (float*)d_out;               // [16384, 2048]

    cudaFuncSetAttribute(gemm_tc, cudaFuncAttributeMaxDynamicSharedMemorySize, SMEM_BYTES);

    xnorm_kernel<<<NB, 128>>>(X);
    wnorm_kernel<<<NO, 128>>>(W);
    gemm_tc<<<dim3(NO / BN, NB / BM), THREADS, SMEM_BYTES>>>(X, W);
    spike_kernel<<<NB, 256>>>(TH, OUT);
}

// round 6
// speedup vs baseline: 1.8236x; 1.5086x over previous
#include <cuda_runtime.h>
#include <cstdint>

#define NB 16384
#define NI 512
#define NO 2048

#define BM 128
#define BN 64
#define BK 32
#define KCH (NI / BK)     // 16
#define THREADS 256
#define USTRIDE 20                         // uint32 (=2 halves) per row incl. pad
#define APLANE_U (128 * USTRIDE)           // 2560 u32
#define BPLANE_U (64 * USTRIDE)            // 1280 u32
#define STAGE_U (2 * APLANE_U + 2 * BPLANE_U)  // 7680 u32 = 30720 B
#define SMEM_BYTES (2 * STAGE_U * 4)       // 61440 B

// ---------------------------------------------------------------------------
// scratch (device globals — no allocations allowed)
// ---------------------------------------------------------------------------
__device__ float g_xinv[NB];
__device__ float g_winv[NO];
__device__ float g_cos[(size_t)NB * NO];

// ---------------------------------------------------------------------------
// helpers
// ---------------------------------------------------------------------------
// fp16 2-split: x = h + l exactly to ~2^-24 relative
__device__ __forceinline__ void f16_split(float x, uint16_t& h, uint16_t& l) {
    asm("cvt.rn.f16.f32 %0, %1;" : "=h"(h) : "f"(x));
    float hf;
    asm("cvt.f32.f16 %0, %1;" : "=f"(hf) : "h"(h));
    const float r = x - hf;
    asm("cvt.rn.f16.f32 %0, %1;" : "=h"(l) : "f"(r));
}
// d += a*b   (m16n8k16 fp16 -> fp32)
__device__ __forceinline__ void mma_acc(float* d, const uint32_t* a, const uint32_t* b) {
    asm volatile(
        "mma.sync.aligned.m16n8k16.row.col.f32.f16.f16.f32 "
        "{%0,%1,%2,%3}, {%4,%5,%6,%7}, {%8,%9}, {%0,%1,%2,%3};"
        : "+f"(d[0]), "+f"(d[1]), "+f"(d[2]), "+f"(d[3])
        : "r"(a[0]), "r"(a[1]), "r"(a[2]), "r"(a[3]), "r"(b[0]), "r"(b[1]));
}
// d = a*b (fresh accumulation chain)
__device__ __forceinline__ void mma_zero(float* d, const uint32_t* a, const uint32_t* b) {
    asm volatile(
        "mma.sync.aligned.m16n8k16.row.col.f32.f16.f16.f32 "
        "{%0,%1,%2,%3}, {%4,%5,%6,%7}, {%8,%9}, {%10,%11,%12,%13};"
        : "=f"(d[0]), "=f"(d[1]), "=f"(d[2]), "=f"(d[3])
        : "r"(a[0]), "r"(a[1]), "r"(a[2]), "r"(a[3]), "r"(b[0]), "r"(b[1]),
          "f"(0.0f), "f"(0.0f), "f"(0.0f), "f"(0.0f));
}

// ---------------------------------------------------------------------------
// Row inverse L2 norms
// ---------------------------------------------------------------------------
__global__ void xnorm_kernel(const float* __restrict__ X) {
    const int row = blockIdx.x;
    float4 v = reinterpret_cast<const float4*>(X + (size_t)row * NI)[threadIdx.x];
    float s = v.x * v.x + v.y * v.y + v.z * v.z + v.w * v.w;
#pragma unroll
    for (int o = 16; o; o >>= 1) s += __shfl_xor_sync(0xffffffffu, s, o);
    __shared__ float ws[4];
    if ((threadIdx.x & 31) == 0) ws[threadIdx.x >> 5] = s;
    __syncthreads();
    if (threadIdx.x == 0) {
        float t = ws[0] + ws[1] + ws[2] + ws[3];
        g_xinv[row] = 1.0f / fmaxf(sqrtf(t), 1e-8f);
    }
}
__global__ void wnorm_kernel(const float* __restrict__ W) {
    const int row = blockIdx.x;
    float4 v = reinterpret_cast<const float4*>(W + (size_t)row * NI)[threadIdx.x];
    float s = v.x * v.x + v.y * v.y + v.z * v.z + v.w * v.w;
#pragma unroll
    for (int o = 16; o; o >>= 1) s += __shfl_xor_sync(0xffffffffu, s, o);
    __shared__ float ws[4];
    if ((threadIdx.x & 31) == 0) ws[threadIdx.x >> 5] = s;
    __syncthreads();
    if (threadIdx.x == 0) {
        float t = ws[0] + ws[1] + ws[2] + ws[3];
        g_winv[row] = 1.0f / fmaxf(sqrtf(t), 1e-8f);
    }
}

// ---------------------------------------------------------------------------
// 3xFP16 warp-mma GEMM (x = h + l; products hh + hl + lh, ll ~2^-24 dropped):
//   cos[b,o] = xinv[b]*winv[o]*dot(X[b,:],W[o,:])
// CTA 128x64x32, 2-stage smem + register prefetch, 8 warps (2m x 4n),
// warp 64x16. Per kc: temp frag (6-MMA chain from zero) flushed into the
// fp32 master accumulator with RN adds on CUDA cores.
// Smem planes hold packed half2 (k-pairs) with USTRIDE=20 u32/row (pad).
// ---------------------------------------------------------------------------
__global__ __launch_bounds__(THREADS, 2)
void gemm_tc(const float* __restrict__ X, const float* __restrict__ W) {
    extern __shared__ uint32_t smem[];   // [2 stages][Ah|Al|Bh|Bl]

    const int tid = threadIdx.x;
    const int wid = tid >> 5;
    const int lane = tid & 31;
    const int m0 = blockIdx.y * BM;
    const int n0 = blockIdx.x * BN;
    const int warpM = wid & 1;   // 2
    const int warpN = wid >> 1;  // 4
    const int g = lane >> 2;     // 0..7
    const int t4 = lane & 3;     // 0..3

    // global-load mapping: 8 threads per row (one float4 = 4 k-values each)
    const int arow[4] = { (0 * THREADS + tid) >> 3, (1 * THREADS + tid) >> 3,
                          (2 * THREADS + tid) >> 3, (3 * THREADS + tid) >> 3 };
    const int brow[2] = { (0 * THREADS + tid) >> 3, (1 * THREADS + tid) >> 3 };
    const int c4 = (tid & 7) * 4;          // k offset of the float4
    const int cu = (tid & 7) * 2;          // u32 offset in plane row

    float master[4][2][4];
#pragma unroll
    for (int i = 0; i < 4; i++)
#pragma unroll
        for (int j = 0; j < 2; j++)
#pragma unroll
            for (int e = 0; e < 4; e++) master[i][j][e] = 0.0f;

    float4 ra[4], rb[2];   // single prefetch register set

    auto ldg = [&](int kc) {
        const int kbase = kc * BK + c4;
#pragma unroll
        for (int t = 0; t < 4; t++)
            ra[t] = *reinterpret_cast<const float4*>(X + (size_t)(m0 + arow[t]) * NI + kbase);
#pragma unroll
        for (int t = 0; t < 2; t++)
            rb[t] = *reinterpret_cast<const float4*>(W + (size_t)(n0 + brow[t]) * NI + kbase);
    };
    auto split_pack = [&](const float4& v, uint32_t& ph0, uint32_t& ph1,
                          uint32_t& pl0, uint32_t& pl1) {
        uint16_t h0, l0, h1, l1, h2, l2, h3, l3;
        f16_split(v.x, h0, l0); f16_split(v.y, h1, l1);
        f16_split(v.z, h2, l2); f16_split(v.w, h3, l3);
        ph0 = (uint32_t)h0 | ((uint32_t)h1 << 16);
        ph1 = (uint32_t)h2 | ((uint32_t)h3 << 16);
        pl0 = (uint32_t)l0 | ((uint32_t)l1 << 16);
        pl1 = (uint32_t)l2 | ((uint32_t)l3 << 16);
    };
    auto sts = [&](int st) {
        uint32_t* Ah = smem + st * STAGE_U;
        uint32_t* Al = Ah + APLANE_U;
        uint32_t* Bh = Al + APLANE_U;
        uint32_t* Bl = Bh + BPLANE_U;
#pragma unroll
        for (int t = 0; t < 4; t++) {
            uint32_t ph0, ph1, pl0, pl1;
            split_pack(ra[t], ph0, ph1, pl0, pl1);
            const int o = arow[t] * USTRIDE + cu;
            *reinterpret_cast<uint2*>(Ah + o) = make_uint2(ph0, ph1);
            *reinterpret_cast<uint2*>(Al + o) = make_uint2(pl0, pl1);
        }
#pragma unroll
        for (int t = 0; t < 2; t++) {
            uint32_t ph0, ph1, pl0, pl1;
            split_pack(rb[t], ph0, ph1, pl0, pl1);
            const int o = brow[t] * USTRIDE + cu;
            *reinterpret_cast<uint2*>(Bh + o) = make_uint2(ph0, ph1);
            *reinterpret_cast<uint2*>(Bl + o) = make_uint2(pl0, pl1);
        }
    };

    ldg(0);
    sts(0);
    ldg(1);

    for (int kc = 0; kc < KCH; kc++) {
        __syncthreads();
        const int cur = kc & 1;
        const uint32_t* Ah = smem + cur * STAGE_U;
        const uint32_t* Al = Ah + APLANE_U;
        const uint32_t* Bh = Al + APLANE_U;
        const uint32_t* Bl = Bh + BPLANE_U;

        float temp[4][2][4];
#pragma unroll
        for (int ks2 = 0; ks2 < 2; ks2++) {      // two k16 steps per kc
            const int ko = ks2 * 8;              // u32 offset (16 halves)
            uint32_t bh[2][2], bl[2][2];
#pragma unroll
            for (int nt = 0; nt < 2; nt++) {
                const int col = warpN * 16 + nt * 8 + g;
                const int base = col * USTRIDE + t4 + ko;
                bh[nt][0] = Bh[base];
                bh[nt][1] = Bh[base + 4];
                bl[nt][0] = Bl[base];
                bl[nt][1] = Bl[base + 4];
            }
#pragma unroll
            for (int mt = 0; mt < 4; mt++) {
                const int row = warpM * 64 + mt * 16 + g;
                const int b0 = row * USTRIDE + t4 + ko;
                const int b8 = (row + 8) * USTRIDE + t4 + ko;
                uint32_t ah[4], al[4];
                ah[0] = Ah[b0];     ah[1] = Ah[b8];
                ah[2] = Ah[b0 + 4]; ah[3] = Ah[b8 + 4];
                al[0] = Al[b0];     al[1] = Al[b8];
                al[2] = Al[b0 + 4]; al[3] = Al[b8 + 4];
#pragma unroll
                for (int nt = 0; nt < 2; nt++) {
                    if (ks2 == 0) mma_zero(temp[mt][nt], ah, bh[nt]);  // h*h fresh
                    else          mma_acc(temp[mt][nt], ah, bh[nt]);
                    mma_acc(temp[mt][nt], ah, bl[nt]);   // h*l
                    mma_acc(temp[mt][nt], al, bh[nt]);   // l*h
                }
            }
        }
        // flush 6-MMA chain into RN fp32 master
#pragma unroll
        for (int mt = 0; mt < 4; mt++)
#pragma unroll
            for (int nt = 0; nt < 2; nt++)
#pragma unroll
                for (int e = 0; e < 4; e++)
                    master[mt][nt][e] += temp[mt][nt][e];

        if (kc + 1 < KCH) {
            sts((kc + 1) & 1);
            if (kc + 2 < KCH) ldg(kc + 2);
        }
    }

    // epilogue: scale by xinv*winv, store cosine (float2 per frag row)
#pragma unroll
    for (int mt = 0; mt < 4; mt++) {
        const int r0 = m0 + warpM * 64 + mt * 16 + g;
        const int r1 = r0 + 8;
        const float xi0 = g_xinv[r0];
        const float xi1 = g_xinv[r1];
#pragma unroll
        for (int nt = 0; nt < 2; nt++) {
            const int c = n0 + warpN * 16 + nt * 8 + t4 * 2;
            const float2 wv = *reinterpret_cast<const float2*>(g_winv + c);
            float2 o0, o1;
            o0.x = master[mt][nt][0] * xi0 * wv.x;
            o0.y = master[mt][nt][1] * xi0 * wv.y;
            o1.x = master[mt][nt][2] * xi1 * wv.x;
            o1.y = master[mt][nt][3] * xi1 * wv.y;
            *reinterpret_cast<float2*>(g_cos + (size_t)r0 * NO + c) = o0;
            *reinterpret_cast<float2*>(g_cos + (size_t)r1 * NO + c) = o1;
        }
    }
}

// ---------------------------------------------------------------------------
// Per-row epilogue: mean/max/argmax over 2048 cosines, nonlinearity,
// adaptive threshold, WTA. One 256-thread block per row; 8 elems/thread.
// ---------------------------------------------------------------------------
__global__ __launch_bounds__(256) void spike_kernel(
    const float* __restrict__ th, float* __restrict__ out) {
    const int row = blockIdx.x;
    const int tid = threadIdx.x;
    const float* crow = g_cos + (size_t)row * NO;
    const int base = tid * 8;

    float v[8];
    *reinterpret_cast<float4*>(&v[0]) = *reinterpret_cast<const float4*>(crow + base);
    *reinterpret_cast<float4*>(&v[4]) = *reinterpret_cast<const float4*>(crow + base + 4);

    float s = 0.0f, mx = -3.402823466e+38f;
    int mi = 0;
#pragma unroll
    for (int e = 0; e < 8; e++) {
        s += v[e];
        if (v[e] > mx) { mx = v[e]; mi = base + e; }
    }
#pragma unroll
    for (int o = 16; o; o >>= 1) {
        s += __shfl_xor_sync(0xffffffffu, s, o);
        float omx = __shfl_xor_sync(0xffffffffu, mx, o);
        int omi = __shfl_xor_sync(0xffffffffu, mi, o);
        if (omx > mx || (omx == mx && omi < mi)) { mx = omx; mi = omi; }
    }
    __shared__ float ssum[8], smax[8];
    __shared__ int sidx[8];
    __shared__ float sh_mu, sh_q;
    __shared__ int sh_arg;
    if ((tid & 31) == 0) { ssum[tid >> 5] = s; smax[tid >> 5] = mx; sidx[tid >> 5] = mi; }
    __syncthreads();
    if (tid == 0) {
        float ts = 0.0f, tm = -3.402823466e+38f;
        int ti = 0;
#pragma unroll
        for (int w = 0; w < 8; w++) {
            ts += ssum[w];
            if (smax[w] > tm || (smax[w] == tm && sidx[w] < ti)) { tm = smax[w]; ti = sidx[w]; }
        }
        const float mu = ts * (1.0f / NO);
        const float c = tm - mu;
        const float a = fabsf(c);
        const float vmax = copysignf((a + 10.0f * a * a * a) * 50.0f, c);
        sh_mu = mu;
        sh_q = vmax * 0.25f;
        sh_arg = ti;
    }
    __syncthreads();
    const float mu = sh_mu;
    const float q = sh_q;
    const int argi = sh_arg;

    float t[8];
    *reinterpret_cast<float4*>(&t[0]) = *reinterpret_cast<const float4*>(th + base);
    *reinterpret_cast<float4*>(&t[4]) = *reinterpret_cast<const float4*>(th + base + 4);

    float sp[8];
    int any = 0;
#pragma unroll
    for (int e = 0; e < 8; e++) {
        const float c = v[e] - mu;
        const float a = fabsf(c);
        const float vm = copysignf((a + 10.0f * a * a * a) * 50.0f, c);
        const float eff = fmaxf(fminf(t[e], q), 0.01f);
        sp[e] = (vm >= eff) ? 1.0f : 0.0f;
        any |= (vm >= eff);
    }
    const int anyb = __syncthreads_or(any);
    if (!anyb) {
#pragma unroll
        for (int e = 0; e < 8; e++) sp[e] = (base + e == argi) ? 1.0f : 0.0f;
    }
    float* dst = out + (size_t)row * NO + base;
    *reinterpret_cast<float4*>(dst) = *reinterpret_cast<float4*>(&sp[0]);
    *reinterpret_cast<float4*>(dst + 4) = *reinterpret_cast<float4*>(&sp[4]);
}

// ---------------------------------------------------------------------------
extern "C" void kernel_launch(void* const* d_in, const int* in_sizes, int n_in,
                              void* d_out, int out_size) {
    const float* X = (const float*)d_in[0];   // [16384, 512]
    const float* W = (const float*)d_in[1];   // [2048, 512]
    const float* TH = (const float*)d_in[2];  // [2048]
    float* OUT = (float*)d_out;               // [16384, 2048]

    cudaFuncSetAttribute(gemm_tc, cudaFuncAttributeMaxDynamicSharedMemorySize, SMEM_BYTES);

    xnorm_kernel<<<NB, 128>>>(X);
    wnorm_kernel<<<NO, 128>>>(W);
    gemm_tc<<<dim3(NO / BN, NB / BM), THREADS, SMEM_BYTES>>>(X, W);
    spike_kernel<<<NB, 256>>>(TH, OUT);
}

// round 7
// speedup vs baseline: 2.1165x; 1.1606x over previous
#include <cuda_runtime.h>
#include <cstdint>

#define NB 16384
#define NI 512
#define NO 2048

#define BM 128
#define BN 64
#define BK 64
#define KCH (NI / BK)     // 8
#define THREADS 256
#define USTRIDE 36                          // u32 per row: 32 data + 4 pad
#define APLANE_U (128 * USTRIDE)            // 4608
#define BPLANE_U (64 * USTRIDE)             // 2304
#define STAGE_U (2 * APLANE_U + 2 * BPLANE_U)  // 13824 u32 = 55296 B
#define SMEM_BYTES (2 * STAGE_U * 4)        // 110592 B

// ---------------------------------------------------------------------------
// scratch (device globals — no allocations allowed)
// ---------------------------------------------------------------------------
__device__ uint16_t g_xh[(size_t)NB * NI];   // fp16 hi plane of x/||x||
__device__ uint16_t g_xl[(size_t)NB * NI];   // fp16 lo plane
__device__ uint16_t g_wh[(size_t)NO * NI];
__device__ uint16_t g_wl[(size_t)NO * NI];
__device__ float g_cos[(size_t)NB * NO];

// ---------------------------------------------------------------------------
// helpers
// ---------------------------------------------------------------------------
__device__ __forceinline__ uint32_t smem_u32(const void* p) {
    uint32_t a;
    asm("{ .reg .u64 t; cvta.to.shared.u64 t, %1; cvt.u32.u64 %0, t; }" : "=r"(a) : "l"(p));
    return a;
}
__device__ __forceinline__ void cp_async16(uint32_t dst, const void* src) {
    asm volatile("cp.async.cg.shared.global [%0], [%1], 16;" :: "r"(dst), "l"(src));
}
__device__ __forceinline__ void cp_commit() {
    asm volatile("cp.async.commit_group;" ::: "memory");
}
template <int N>
__device__ __forceinline__ void cp_wait() {
    asm volatile("cp.async.wait_group %0;" :: "n"(N) : "memory");
}
// fp16 2-split: x = h + l (exact to ~2^-24 relative)
__device__ __forceinline__ void f16_split(float x, uint16_t& h, uint16_t& l) {
    asm("cvt.rn.f16.f32 %0, %1;" : "=h"(h) : "f"(x));
    float hf;
    asm("cvt.f32.f16 %0, %1;" : "=f"(hf) : "h"(h));
    const float r = x - hf;
    asm("cvt.rn.f16.f32 %0, %1;" : "=h"(l) : "f"(r));
}
// d += a*b   (m16n8k16 fp16 -> fp32)
__device__ __forceinline__ void mma_acc(float* d, const uint32_t* a, const uint32_t* b) {
    asm volatile(
        "mma.sync.aligned.m16n8k16.row.col.f32.f16.f16.f32 "
        "{%0,%1,%2,%3}, {%4,%5,%6,%7}, {%8,%9}, {%0,%1,%2,%3};"
        : "+f"(d[0]), "+f"(d[1]), "+f"(d[2]), "+f"(d[3])
        : "r"(a[0]), "r"(a[1]), "r"(a[2]), "r"(a[3]), "r"(b[0]), "r"(b[1]));
}
// d = a*b (fresh accumulation chain)
__device__ __forceinline__ void mma_zero(float* d, const uint32_t* a, const uint32_t* b) {
    asm volatile(
        "mma.sync.aligned.m16n8k16.row.col.f32.f16.f16.f32 "
        "{%0,%1,%2,%3}, {%4,%5,%6,%7}, {%8,%9}, {%10,%11,%12,%13};"
        : "=f"(d[0]), "=f"(d[1]), "=f"(d[2]), "=f"(d[3])
        : "r"(a[0]), "r"(a[1]), "r"(a[2]), "r"(a[3]), "r"(b[0]), "r"(b[1]),
          "f"(0.0f), "f"(0.0f), "f"(0.0f), "f"(0.0f));
}

// ---------------------------------------------------------------------------
// prep: normalize each row (/(max(||row||, eps))) and write fp16 hi/lo planes.
// One 128-thread block per row; 4 elements (one float4) per thread.
// ---------------------------------------------------------------------------
__global__ __launch_bounds__(128) void prep_kernel(
    const float* __restrict__ src, uint16_t* __restrict__ Hi,
    uint16_t* __restrict__ Lo) {
    const int row = blockIdx.x;
    const int tid = threadIdx.x;
    const float4 v = reinterpret_cast<const float4*>(src + (size_t)row * NI)[tid];
    float s = v.x * v.x + v.y * v.y + v.z * v.z + v.w * v.w;
#pragma unroll
    for (int o = 16; o; o >>= 1) s += __shfl_xor_sync(0xffffffffu, s, o);
    __shared__ float ws[4];
    __shared__ float sh_inv;
    if ((tid & 31) == 0) ws[tid >> 5] = s;
    __syncthreads();
    if (tid == 0) {
        const float t = ws[0] + ws[1] + ws[2] + ws[3];
        sh_inv = 1.0f / fmaxf(sqrtf(t), 1e-8f);
    }
    __syncthreads();
    const float inv = sh_inv;

    uint16_t h0, l0, h1, l1, h2, l2, h3, l3;
    f16_split(v.x * inv, h0, l0);
    f16_split(v.y * inv, h1, l1);
    f16_split(v.z * inv, h2, l2);
    f16_split(v.w * inv, h3, l3);
    uint2 ph, pl;
    ph.x = (uint32_t)h0 | ((uint32_t)h1 << 16);
    ph.y = (uint32_t)h2 | ((uint32_t)h3 << 16);
    pl.x = (uint32_t)l0 | ((uint32_t)l1 << 16);
    pl.y = (uint32_t)l2 | ((uint32_t)l3 << 16);
    reinterpret_cast<uint2*>(Hi + (size_t)row * NI)[tid] = ph;
    reinterpret_cast<uint2*>(Lo + (size_t)row * NI)[tid] = pl;
}

// ---------------------------------------------------------------------------
// 3xFP16 warp-mma GEMM on pre-normalized pre-split planes:
//   cos[b,o] = dot(xn[b,:], wn[o,:])  via hh + hl + lh
// CTA 128x64x64, 2-stage cp.async smem, 8 warps (2m x 4n), warp 64x16.
// 6-MMA temp chains (zeroed at k16-steps 0 and 2, RN-flushed after 1 and 3).
// ---------------------------------------------------------------------------
__global__ __launch_bounds__(THREADS, 2)
void gemm_tc() {
    extern __shared__ uint32_t smem[];   // [2 stages][Ah|Al|Bh|Bl]
    const uint32_t sbase = smem_u32(smem);

    const int tid = threadIdx.x;
    const int wid = tid >> 5;
    const int lane = tid & 31;
    const int m0 = blockIdx.y * BM;
    const int n0 = blockIdx.x * BN;
    const int warpM = wid & 1;   // 2
    const int warpN = wid >> 1;  // 4
    const int g = lane >> 2;     // 0..7
    const int t4 = lane & 3;     // 0..3

    float master[4][2][4];
#pragma unroll
    for (int i = 0; i < 4; i++)
#pragma unroll
        for (int j = 0; j < 2; j++)
#pragma unroll
            for (int e = 0; e < 4; e++) master[i][j][e] = 0.0f;

    // cp.async fill: 3072 16-B chunks per stage, 12 per thread.
    // gid 0..1023 Ah | 1024..2047 Al | 2048..2559 Bh | 2560..3071 Bl
    auto issue = [&](int kc, int st) {
        const int kh = kc * BK;                 // half-offset within a row
        const uint32_t sb = sbase + (uint32_t)(st * STAGE_U) * 4u;
#pragma unroll
        for (int t = 0; t < 12; t++) {
            const int gid = t * THREADS + tid;
            const uint16_t* srcp;
            uint32_t dst;
            if (gid < 1024) {
                const int row = gid >> 3, c = gid & 7;
                srcp = g_xh + (size_t)(m0 + row) * NI + kh + c * 8;
                dst = sb + (uint32_t)(row * USTRIDE + c * 4) * 4u;
            } else if (gid < 2048) {
                const int j = gid - 1024;
                const int row = j >> 3, c = j & 7;
                srcp = g_xl + (size_t)(m0 + row) * NI + kh + c * 8;
                dst = sb + (uint32_t)(APLANE_U + row * USTRIDE + c * 4) * 4u;
            } else if (gid < 2560) {
                const int j = gid - 2048;
                const int row = j >> 3, c = j & 7;
                srcp = g_wh + (size_t)(n0 + row) * NI + kh + c * 8;
                dst = sb + (uint32_t)(2 * APLANE_U + row * USTRIDE + c * 4) * 4u;
            } else {
                const int j = gid - 2560;
                const int row = j >> 3, c = j & 7;
                srcp = g_wl + (size_t)(n0 + row) * NI + kh + c * 8;
                dst = sb + (uint32_t)(2 * APLANE_U + BPLANE_U + row * USTRIDE + c * 4) * 4u;
            }
            cp_async16(dst, srcp);
        }
        cp_commit();
    };

    issue(0, 0);
    issue(1, 1);

    for (int kc = 0; kc < KCH; kc++) {
        cp_wait<1>();
        __syncthreads();
        const int cur = kc & 1;
        const uint32_t* Ah = smem + cur * STAGE_U;
        const uint32_t* Al = Ah + APLANE_U;
        const uint32_t* Bh = Al + APLANE_U;
        const uint32_t* Bl = Bh + BPLANE_U;

        float temp[4][2][4];
#pragma unroll
        for (int s = 0; s < 4; s++) {            // four k16 steps
            const int ko = s * 8;                // u32 offset (16 halves)
            uint32_t bh[2][2], bl[2][2];
#pragma unroll
            for (int nt = 0; nt < 2; nt++) {
                const int col = warpN * 16 + nt * 8 + g;
                const int base = col * USTRIDE + t4 + ko;
                bh[nt][0] = Bh[base];
                bh[nt][1] = Bh[base + 4];
                bl[nt][0] = Bl[base];
                bl[nt][1] = Bl[base + 4];
            }
#pragma unroll
            for (int mt = 0; mt < 4; mt++) {
                const int row = warpM * 64 + mt * 16 + g;
                const int b0 = row * USTRIDE + t4 + ko;
                const int b8 = (row + 8) * USTRIDE + t4 + ko;
                uint32_t ah[4], al[4];
                ah[0] = Ah[b0];     ah[1] = Ah[b8];
                ah[2] = Ah[b0 + 4]; ah[3] = Ah[b8 + 4];
                al[0] = Al[b0];     al[1] = Al[b8];
                al[2] = Al[b0 + 4]; al[3] = Al[b8 + 4];
#pragma unroll
                for (int nt = 0; nt < 2; nt++) {
                    if ((s & 1) == 0) mma_zero(temp[mt][nt], ah, bh[nt]);  // fresh chain
                    else              mma_acc(temp[mt][nt], ah, bh[nt]);
                    mma_acc(temp[mt][nt], ah, bl[nt]);   // h*l
                    mma_acc(temp[mt][nt], al, bh[nt]);   // l*h
                }
            }
            if (s & 1) {   // flush 6-MMA chain into RN fp32 master
#pragma unroll
                for (int mt = 0; mt < 4; mt++)
#pragma unroll
                    for (int nt = 0; nt < 2; nt++)
#pragma unroll
                        for (int e = 0; e < 4; e++)
                            master[mt][nt][e] += temp[mt][nt][e];
            }
        }
        __syncthreads();
        if (kc + 2 < KCH) issue(kc + 2, cur);
        else cp_commit();   // keep wait_group accounting uniform
    }

    // epilogue: planes are pre-normalized, so master IS the cosine
#pragma unroll
    for (int mt = 0; mt < 4; mt++) {
        const int r0 = m0 + warpM * 64 + mt * 16 + g;
        const int r1 = r0 + 8;
#pragma unroll
        for (int nt = 0; nt < 2; nt++) {
            const int c = n0 + warpN * 16 + nt * 8 + t4 * 2;
            float2 o0, o1;
            o0.x = master[mt][nt][0]; o0.y = master[mt][nt][1];
            o1.x = master[mt][nt][2]; o1.y = master[mt][nt][3];
            *reinterpret_cast<float2*>(g_cos + (size_t)r0 * NO + c) = o0;
            *reinterpret_cast<float2*>(g_cos + (size_t)r1 * NO + c) = o1;
        }
    }
}

// ---------------------------------------------------------------------------
// Per-row epilogue, 2 rows per block (loads for both rows in flight together):
// mean/max/argmax over 2048 cosines, nonlinearity, adaptive threshold, WTA.
// 256 threads; 8 elems/thread/row.
// ---------------------------------------------------------------------------
__global__ __launch_bounds__(256) void spike_kernel(
    const float* __restrict__ th, float* __restrict__ out) {
    const int r0 = blockIdx.x * 2;
    const int r1 = r0 + 1;
    const int tid = threadIdx.x;
    const int base = tid * 8;
    const float* c0 = g_cos + (size_t)r0 * NO + base;
    const float* c1 = g_cos + (size_t)r1 * NO + base;

    float v0[8], v1[8];
    *reinterpret_cast<float4*>(&v0[0]) = *reinterpret_cast<const float4*>(c0);
    *reinterpret_cast<float4*>(&v0[4]) = *reinterpret_cast<const float4*>(c0 + 4);
    *reinterpret_cast<float4*>(&v1[0]) = *reinterpret_cast<const float4*>(c1);
    *reinterpret_cast<float4*>(&v1[4]) = *reinterpret_cast<const float4*>(c1 + 4);

    float s0 = 0.0f, s1 = 0.0f;
    float mx0 = -3.402823466e+38f, mx1 = -3.402823466e+38f;
    int i0 = 0, i1 = 0;
#pragma unroll
    for (int e = 0; e < 8; e++) {
        s0 += v0[e];
        if (v0[e] > mx0) { mx0 = v0[e]; i0 = base + e; }
        s1 += v1[e];
        if (v1[e] > mx1) { mx1 = v1[e]; i1 = base + e; }
    }
#pragma unroll
    for (int o = 16; o; o >>= 1) {
        s0 += __shfl_xor_sync(0xffffffffu, s0, o);
        s1 += __shfl_xor_sync(0xffffffffu, s1, o);
        float om = __shfl_xor_sync(0xffffffffu, mx0, o);
        int oi = __shfl_xor_sync(0xffffffffu, i0, o);
        if (om > mx0 || (om == mx0 && oi < i0)) { mx0 = om; i0 = oi; }
        om = __shfl_xor_sync(0xffffffffu, mx1, o);
        oi = __shfl_xor_sync(0xffffffffu, i1, o);
        if (om > mx1 || (om == mx1 && oi < i1)) { mx1 = om; i1 = oi; }
    }
    __shared__ float ssum[2][8], smax[2][8];
    __shared__ int sidx[2][8];
    __shared__ float sh_mu[2], sh_q[2];
    __shared__ int sh_arg[2];
    if ((tid & 31) == 0) {
        const int w = tid >> 5;
        ssum[0][w] = s0; smax[0][w] = mx0; sidx[0][w] = i0;
        ssum[1][w] = s1; smax[1][w] = mx1; sidx[1][w] = i1;
    }
    __syncthreads();
    if (tid == 0 || tid == 32) {          // warp0 finalizes row0, warp1 row1
        const int r = tid >> 5;
        float ts = 0.0f, tm = -3.402823466e+38f;
        int ti = 0;
#pragma unroll
        for (int w = 0; w < 8; w++) {
            ts += ssum[r][w];
            if (smax[r][w] > tm || (smax[r][w] == tm && sidx[r][w] < ti)) {
                tm = smax[r][w]; ti = sidx[r][w];
            }
        }
        const float mu = ts * (1.0f / NO);
        const float c = tm - mu;
        const float a = fabsf(c);
        const float vmax = copysignf((a + 10.0f * a * a * a) * 50.0f, c);
        sh_mu[r] = mu;
        sh_q[r] = vmax * 0.25f;
        sh_arg[r] = ti;
    }
    __syncthreads();

    float t[8];
    *reinterpret_cast<float4*>(&t[0]) = *reinterpret_cast<const float4*>(th + base);
    *reinterpret_cast<float4*>(&t[4]) = *reinterpret_cast<const float4*>(th + base + 4);

    const float mu0 = sh_mu[0], q0 = sh_q[0];
    const float mu1 = sh_mu[1], q1 = sh_q[1];
    float sp0[8], sp1[8];
    int any0 = 0, any1 = 0;
#pragma unroll
    for (int e = 0; e < 8; e++) {
        float c = v0[e] - mu0;
        float a = fabsf(c);
        float vm = copysignf((a + 10.0f * a * a * a) * 50.0f, c);
        float eff = fmaxf(fminf(t[e], q0), 0.01f);
        sp0[e] = (vm >= eff) ? 1.0f : 0.0f;
        any0 |= (vm >= eff);
        c = v1[e] - mu1;
        a = fabsf(c);
        vm = copysignf((a + 10.0f * a * a * a) * 50.0f, c);
        eff = fmaxf(fminf(t[e], q1), 0.01f);
        sp1[e] = (vm >= eff) ? 1.0f : 0.0f;
        any1 |= (vm >= eff);
    }
    const int ab0 = __syncthreads_or(any0);
    const int ab1 = __syncthreads_or(any1);
    if (!ab0) {
        const int argi = sh_arg[0];
#pragma unroll
        for (int e = 0; e < 8; e++) sp0[e] = (base + e == argi) ? 1.0f : 0.0f;
    }
    if (!ab1) {
        const int argi = sh_arg[1];
#pragma unroll
        for (int e = 0; e < 8; e++) sp1[e] = (base + e == argi) ? 1.0f : 0.0f;
    }
    float* d0 = out + (size_t)r0 * NO + base;
    float* d1 = out + (size_t)r1 * NO + base;
    *reinterpret_cast<float4*>(d0) = *reinterpret_cast<float4*>(&sp0[0]);
    *reinterpret_cast<float4*>(d0 + 4) = *reinterpret_cast<float4*>(&sp0[4]);
    *reinterpret_cast<float4*>(d1) = *reinterpret_cast<float4*>(&sp1[0]);
    *reinterpret_cast<float4*>(d1 + 4) = *reinterpret_cast<float4*>(&sp1[4]);
}

// ---------------------------------------------------------------------------
extern "C" void kernel_launch(void* const* d_in, const int* in_sizes, int n_in,
                              void* d_out, int out_size) {
    const float* X = (const float*)d_in[0];   // [16384, 512]
    const float* W = (const float*)d_in[1];   // [2048, 512]
    const float* TH = (const float*)d_in[2];  // [2048]
    float* OUT = (float*)d_out;               // [16384, 2048]

    uint16_t *xh, *xl, *wh, *wl;
    cudaGetSymbolAddress((void**)&xh, g_xh);
    cudaGetSymbolAddress((void**)&xl, g_xl);
    cudaGetSymbolAddress((void**)&wh, g_wh);
    cudaGetSymbolAddress((void**)&wl, g_wl);

    cudaFuncSetAttribute(gemm_tc, cudaFuncAttributeMaxDynamicSharedMemorySize, SMEM_BYTES);

    prep_kernel<<<NB, 128>>>(X, xh, xl);
    prep_kernel<<<NO, 128>>>(W, wh, wl);
    gemm_tc<<<dim3(NO / BN, NB / BM), THREADS, SMEM_BYTES>>>();
    spike_kernel<<<NB / 2, 256>>>(TH, OUT);
}